// round 3
// baseline (speedup 1.0000x reference)
#include <cuda_runtime.h>
#include <cstdint>

#define N_NODES 100000
#define N_EDGES 1600000
#define F 128

// Scratch (allocation-free rule: __device__ globals).
// __align__(16): accessed via float4* and red.global.add.v4.f32.
__device__ __align__(16) float g_agg[(size_t)N_NODES * F];   // 51.2 MB
__device__ __align__(16) float g_h1[(size_t)N_NODES * F];    // 51.2 MB
__device__ int   g_deg_src[N_NODES];
__device__ int   g_deg_dst[N_NODES];
__device__ float g_rs_src[N_NODES];
__device__ float g_rs_dst[N_NODES];

__global__ void zero_degs_kernel() {
    int i = blockIdx.x * blockDim.x + threadIdx.x;
    if (i < N_NODES) { g_deg_src[i] = 0; g_deg_dst[i] = 0; }
}

// NOTE: src/dst are int32 — JAX's default x64-disable downcasts the reference's
// "int64" randint arrays to int32.
__global__ void count_degs_kernel(const int* __restrict__ src,
                                  const int* __restrict__ dst) {
    int e = blockIdx.x * blockDim.x + threadIdx.x;
    if (e < N_EDGES) {
        atomicAdd(&g_deg_src[src[e]], 1);
        atomicAdd(&g_deg_dst[dst[e]], 1);
    }
}

__global__ void rsqrt_degs_kernel() {
    int i = blockIdx.x * blockDim.x + threadIdx.x;
    if (i < N_NODES) {
        int ds = g_deg_src[i]; if (ds < 1) ds = 1;
        int dd = g_deg_dst[i]; if (dd < 1) dd = 1;
        g_rs_src[i] = rsqrtf((float)ds);
        g_rs_dst[i] = rsqrtf((float)dd);
    }
}

__global__ void zero_agg_kernel() {
    size_t i = (size_t)blockIdx.x * blockDim.x + threadIdx.x;  // float4 index
    if (i < (size_t)N_NODES * (F / 4)) {
        ((float4*)g_agg)[i] = make_float4(0.f, 0.f, 0.f, 0.f);
    }
}

// One warp per edge. Each lane: gather one float4 of the src row (scaled by
// rsqrt(out_deg[src])) and vector-reduce into the dst row.
__global__ void scatter_kernel(const float* __restrict__ h,
                               const int* __restrict__ src,
                               const int* __restrict__ dst) {
    int warp = (blockIdx.x * blockDim.x + threadIdx.x) >> 5;
    int lane = threadIdx.x & 31;
    if (warp >= N_EDGES) return;

    int s = __ldg(&src[warp]);   // all lanes same addr -> broadcast
    int d = __ldg(&dst[warp]);
    float r = __ldg(&g_rs_src[s]);

    float4 v = __ldg(((const float4*)(h + (size_t)s * F)) + lane);
    v.x *= r; v.y *= r; v.z *= r; v.w *= r;

    float* ap = g_agg + (size_t)d * F + (size_t)lane * 4;
    asm volatile("red.global.add.v4.f32 [%0], {%1,%2,%3,%4};"
                 :: "l"(ap), "f"(v.x), "f"(v.y), "f"(v.z), "f"(v.w)
                 : "memory");
}

// out[row,:] = relu( (agg[row,:] * rs_dst[row]) @ W + b )
// BM=64 rows per block, full K=128, full N=128. 256 threads.
// smem: As 64x128 (32 KB) + Ws 128x128 (64 KB) = 96 KB dynamic.
__global__ void __launch_bounds__(256, 2)
gemm_bias_relu_kernel(const float* __restrict__ A,
                      const float* __restrict__ W,
                      const float* __restrict__ b,
                      float* __restrict__ out) {
    extern __shared__ float smem[];
    float* As = smem;              // [64][128]
    float* Ws = smem + 64 * F;     // [128][128]

    int tid  = threadIdx.x;
    int row0 = blockIdx.x * 64;

    // Load W (128x128 = 4096 float4)
    {
        const float4* Wd = (const float4*)W;
        float4* Wsm = (float4*)Ws;
        #pragma unroll
        for (int i = tid; i < 128 * 32; i += 256) Wsm[i] = Wd[i];
    }
    // Load A tile, scaled by rs_dst[row]
    {
        const float4* Ad = (const float4*)A;
        float4* Asm = (float4*)As;
        #pragma unroll
        for (int i = tid; i < 64 * 32; i += 256) {
            int r = i >> 5, c = i & 31;
            int row = row0 + r;
            float4 v = make_float4(0.f, 0.f, 0.f, 0.f);
            if (row < N_NODES) {
                v = Ad[(size_t)row * 32 + c];
                float sc = g_rs_dst[row];
                v.x *= sc; v.y *= sc; v.z *= sc; v.w *= sc;
            }
            Asm[i] = v;
        }
    }
    __syncthreads();

    int tx = tid & 31;   // column group: cols [tx*4, tx*4+4)
    int ty = tid >> 5;   // row group: rows [row0 + ty*8, +8)

    float acc[8][4];
    #pragma unroll
    for (int r = 0; r < 8; ++r)
        #pragma unroll
        for (int c = 0; c < 4; ++c) acc[r][c] = 0.f;

    const float4* Wsm4 = (const float4*)Ws;
    #pragma unroll 4
    for (int k = 0; k < F; ++k) {
        float4 w = Wsm4[k * 32 + tx];
        #pragma unroll
        for (int r = 0; r < 8; ++r) {
            float a = As[(ty * 8 + r) * F + k];   // warp-broadcast
            acc[r][0] += a * w.x;
            acc[r][1] += a * w.y;
            acc[r][2] += a * w.z;
            acc[r][3] += a * w.w;
        }
    }

    float4 bias = ((const float4*)b)[tx];
    #pragma unroll
    for (int r = 0; r < 8; ++r) {
        int row = row0 + ty * 8 + r;
        if (row < N_NODES) {
            float4 o;
            o.x = fmaxf(acc[r][0] + bias.x, 0.f);
            o.y = fmaxf(acc[r][1] + bias.y, 0.f);
            o.z = fmaxf(acc[r][2] + bias.z, 0.f);
            o.w = fmaxf(acc[r][3] + bias.w, 0.f);
            ((float4*)(out + (size_t)row * F))[tx] = o;
        }
    }
}

extern "C" void kernel_launch(void* const* d_in, const int* in_sizes, int n_in,
                              void* d_out, int out_size) {
    const float* features = (const float*)d_in[0];
    const float* W1       = (const float*)d_in[1];
    const float* b1       = (const float*)d_in[2];
    const float* W2       = (const float*)d_in[3];
    const float* b2       = (const float*)d_in[4];
    const int*   src      = (const int*)d_in[5];
    const int*   dst      = (const int*)d_in[6];
    float*       out      = (float*)d_out;

    float* agg = nullptr;
    float* h1  = nullptr;
    cudaGetSymbolAddress((void**)&agg, g_agg);
    cudaGetSymbolAddress((void**)&h1,  g_h1);

    // Idempotent, not a stream op; safe on every call (incl. capture).
    cudaFuncSetAttribute(gemm_bias_relu_kernel,
                         cudaFuncAttributeMaxDynamicSharedMemorySize,
                         (64 * F + F * F) * (int)sizeof(float));

    const int GEMM_SMEM = (64 * F + F * F) * (int)sizeof(float);  // 96 KB

    int nblk_nodes = (N_NODES + 255) / 256;
    int nblk_edges = (N_EDGES + 255) / 256;
    int nblk_aggz  = (int)(((size_t)N_NODES * (F / 4) + 255) / 256);
    int nblk_scat  = (N_EDGES * 32 + 255) / 256;   // one warp per edge
    int nblk_gemm  = (N_NODES + 63) / 64;

    // Degrees (same every call -> deterministic)
    zero_degs_kernel<<<nblk_nodes, 256>>>();
    count_degs_kernel<<<nblk_edges, 256>>>(src, dst);
    rsqrt_degs_kernel<<<nblk_nodes, 256>>>();

    // Layer 1
    zero_agg_kernel<<<nblk_aggz, 256>>>();
    scatter_kernel<<<nblk_scat, 256>>>(features, src, dst);
    gemm_bias_relu_kernel<<<nblk_gemm, 256, GEMM_SMEM>>>(agg, W1, b1, h1);

    // Layer 2
    zero_agg_kernel<<<nblk_aggz, 256>>>();
    scatter_kernel<<<nblk_scat, 256>>>(h1, src, dst);
    gemm_bias_relu_kernel<<<nblk_gemm, 256, GEMM_SMEM>>>(agg, W2, b2, out);
}

// round 4
// speedup vs baseline: 1.7378x; 1.7378x over previous
#include <cuda_runtime.h>
#include <cstdint>

#define N_NODES 100000
#define N_EDGES 1600000
#define F 128
#define SCAN_B 1024
#define NPART ((N_NODES + SCAN_B - 1) / SCAN_B)   // 98

// Scratch (allocation-free rule: __device__ globals).
__device__ __align__(16) float g_agg[(size_t)N_NODES * F];   // 51.2 MB
__device__ __align__(16) float g_h1[(size_t)N_NODES * F];    // 51.2 MB
__device__ int   g_deg_src[N_NODES];
__device__ int   g_deg_dst[N_NODES];
__device__ float g_rs_src[N_NODES];
__device__ float g_rs_dst[N_NODES];
__device__ int   g_rowptr[N_NODES + 1];
__device__ int   g_cursor[N_NODES];
__device__ int   g_col[N_EDGES];                  // 6.4 MB
__device__ int   g_part[NPART];

__global__ void zero_degs_kernel() {
    int i = blockIdx.x * blockDim.x + threadIdx.x;
    if (i < N_NODES) { g_deg_src[i] = 0; g_deg_dst[i] = 0; }
}

// src/dst are int32 (JAX x64-disable downcasts the reference's int64 arrays).
__global__ void count_degs_kernel(const int* __restrict__ src,
                                  const int* __restrict__ dst) {
    int e = blockIdx.x * blockDim.x + threadIdx.x;
    if (e < N_EDGES) {
        atomicAdd(&g_deg_src[src[e]], 1);
        atomicAdd(&g_deg_dst[dst[e]], 1);
    }
}

__global__ void rsqrt_degs_kernel() {
    int i = blockIdx.x * blockDim.x + threadIdx.x;
    if (i < N_NODES) {
        int ds = g_deg_src[i]; if (ds < 1) ds = 1;
        int dd = g_deg_dst[i]; if (dd < 1) dd = 1;
        g_rs_src[i] = rsqrtf((float)ds);
        g_rs_dst[i] = rsqrtf((float)dd);
    }
}

// ---- Exclusive scan of g_deg_dst -> g_rowptr (3 kernels) ----
__global__ void scan_block_sums_kernel() {
    __shared__ int sh[SCAN_B];
    int i = blockIdx.x * SCAN_B + threadIdx.x;
    sh[threadIdx.x] = (i < N_NODES) ? g_deg_dst[i] : 0;
    __syncthreads();
    #pragma unroll
    for (int s = SCAN_B / 2; s > 0; s >>= 1) {
        if (threadIdx.x < s) sh[threadIdx.x] += sh[threadIdx.x + s];
        __syncthreads();
    }
    if (threadIdx.x == 0) g_part[blockIdx.x] = sh[0];
}

__global__ void scan_partials_kernel() {
    if (blockIdx.x == 0 && threadIdx.x == 0) {
        int run = 0;
        for (int i = 0; i < NPART; ++i) { int t = g_part[i]; g_part[i] = run; run += t; }
        g_rowptr[N_NODES] = N_EDGES;
    }
}

__global__ void scan_final_kernel() {
    __shared__ int sh[SCAN_B];
    int tid = threadIdx.x;
    int i = blockIdx.x * SCAN_B + tid;
    int v = (i < N_NODES) ? g_deg_dst[i] : 0;
    sh[tid] = v;
    __syncthreads();
    // inclusive Hillis-Steele
    #pragma unroll
    for (int off = 1; off < SCAN_B; off <<= 1) {
        int t = (tid >= off) ? sh[tid - off] : 0;
        __syncthreads();
        sh[tid] += t;
        __syncthreads();
    }
    if (i < N_NODES) {
        int excl = sh[tid] - v + g_part[blockIdx.x];
        g_rowptr[i] = excl;
        g_cursor[i] = excl;
    }
}

__global__ void fill_csr_kernel(const int* __restrict__ src,
                                const int* __restrict__ dst) {
    int e = blockIdx.x * blockDim.x + threadIdx.x;
    if (e < N_EDGES) {
        int pos = atomicAdd(&g_cursor[dst[e]], 1);
        g_col[pos] = src[e];
    }
}

// ---- Aggregation: one warp per dst node, gather-side reduce ----
// agg[n,:] = rs_dst[n] * sum_{s in N_in(n)} rs_src[s] * h[s,:]
__global__ void __launch_bounds__(256)
aggregate_kernel(const float* __restrict__ h, float* __restrict__ out) {
    int warp = (blockIdx.x * blockDim.x + threadIdx.x) >> 5;
    int lane = threadIdx.x & 31;
    if (warp >= N_NODES) return;

    int beg = __ldg(&g_rowptr[warp]);     // broadcast loads
    int end = __ldg(&g_rowptr[warp + 1]);

    float4 acc = make_float4(0.f, 0.f, 0.f, 0.f);
    int e = beg;
    for (; e + 1 < end; e += 2) {
        int s0 = __ldg(&g_col[e]);
        int s1 = __ldg(&g_col[e + 1]);
        float r0 = __ldg(&g_rs_src[s0]);
        float r1 = __ldg(&g_rs_src[s1]);
        float4 v0 = __ldg(((const float4*)(h + (size_t)s0 * F)) + lane);
        float4 v1 = __ldg(((const float4*)(h + (size_t)s1 * F)) + lane);
        acc.x = fmaf(r0, v0.x, acc.x); acc.y = fmaf(r0, v0.y, acc.y);
        acc.z = fmaf(r0, v0.z, acc.z); acc.w = fmaf(r0, v0.w, acc.w);
        acc.x = fmaf(r1, v1.x, acc.x); acc.y = fmaf(r1, v1.y, acc.y);
        acc.z = fmaf(r1, v1.z, acc.z); acc.w = fmaf(r1, v1.w, acc.w);
    }
    if (e < end) {
        int s0 = __ldg(&g_col[e]);
        float r0 = __ldg(&g_rs_src[s0]);
        float4 v0 = __ldg(((const float4*)(h + (size_t)s0 * F)) + lane);
        acc.x = fmaf(r0, v0.x, acc.x); acc.y = fmaf(r0, v0.y, acc.y);
        acc.z = fmaf(r0, v0.z, acc.z); acc.w = fmaf(r0, v0.w, acc.w);
    }

    float rd = __ldg(&g_rs_dst[warp]);
    acc.x *= rd; acc.y *= rd; acc.z *= rd; acc.w *= rd;
    ((float4*)(out + (size_t)warp * F))[lane] = acc;
}

// out[row,:] = relu( A[row,:] @ W + b ); A is already fully normalized.
// BM=64, full K=N=128 in smem (96 KB). 256 threads, 8x4 reg tile.
__global__ void __launch_bounds__(256, 2)
gemm_bias_relu_kernel(const float* __restrict__ A,
                      const float* __restrict__ W,
                      const float* __restrict__ b,
                      float* __restrict__ out) {
    extern __shared__ float smem[];
    float* As = smem;              // [64][128]
    float* Ws = smem + 64 * F;     // [128][128]

    int tid  = threadIdx.x;
    int row0 = blockIdx.x * 64;

    {
        const float4* Wd = (const float4*)W;
        float4* Wsm = (float4*)Ws;
        #pragma unroll
        for (int i = tid; i < 128 * 32; i += 256) Wsm[i] = Wd[i];
    }
    {
        const float4* Ad = (const float4*)A;
        float4* Asm = (float4*)As;
        #pragma unroll
        for (int i = tid; i < 64 * 32; i += 256) {
            int r = i >> 5, c = i & 31;
            int row = row0 + r;
            float4 v = make_float4(0.f, 0.f, 0.f, 0.f);
            if (row < N_NODES) v = Ad[(size_t)row * 32 + c];
            Asm[i] = v;
        }
    }
    __syncthreads();

    int tx = tid & 31;   // cols [tx*4, tx*4+4)
    int ty = tid >> 5;   // rows [row0 + ty*8, +8)

    float acc[8][4];
    #pragma unroll
    for (int r = 0; r < 8; ++r)
        #pragma unroll
        for (int c = 0; c < 4; ++c) acc[r][c] = 0.f;

    const float4* Wsm4 = (const float4*)Ws;
    #pragma unroll 4
    for (int k = 0; k < F; ++k) {
        float4 w = Wsm4[k * 32 + tx];
        #pragma unroll
        for (int r = 0; r < 8; ++r) {
            float a = As[(ty * 8 + r) * F + k];
            acc[r][0] = fmaf(a, w.x, acc[r][0]);
            acc[r][1] = fmaf(a, w.y, acc[r][1]);
            acc[r][2] = fmaf(a, w.z, acc[r][2]);
            acc[r][3] = fmaf(a, w.w, acc[r][3]);
        }
    }

    float4 bias = ((const float4*)b)[tx];
    #pragma unroll
    for (int r = 0; r < 8; ++r) {
        int row = row0 + ty * 8 + r;
        if (row < N_NODES) {
            float4 o;
            o.x = fmaxf(acc[r][0] + bias.x, 0.f);
            o.y = fmaxf(acc[r][1] + bias.y, 0.f);
            o.z = fmaxf(acc[r][2] + bias.z, 0.f);
            o.w = fmaxf(acc[r][3] + bias.w, 0.f);
            ((float4*)(out + (size_t)row * F))[tx] = o;
        }
    }
}

extern "C" void kernel_launch(void* const* d_in, const int* in_sizes, int n_in,
                              void* d_out, int out_size) {
    const float* features = (const float*)d_in[0];
    const float* W1       = (const float*)d_in[1];
    const float* b1       = (const float*)d_in[2];
    const float* W2       = (const float*)d_in[3];
    const float* b2       = (const float*)d_in[4];
    const int*   src      = (const int*)d_in[5];
    const int*   dst      = (const int*)d_in[6];
    float*       out      = (float*)d_out;

    float* agg = nullptr;
    float* h1  = nullptr;
    cudaGetSymbolAddress((void**)&agg, g_agg);
    cudaGetSymbolAddress((void**)&h1,  g_h1);

    cudaFuncSetAttribute(gemm_bias_relu_kernel,
                         cudaFuncAttributeMaxDynamicSharedMemorySize,
                         (64 * F + F * F) * (int)sizeof(float));
    const int GEMM_SMEM = (64 * F + F * F) * (int)sizeof(float);  // 96 KB

    int nblk_nodes = (N_NODES + 255) / 256;
    int nblk_edges = (N_EDGES + 255) / 256;
    int nblk_aggw  = (N_NODES * 32 + 255) / 256;   // one warp per node
    int nblk_gemm  = (N_NODES + 63) / 64;

    // Degrees + CSR build (same every call -> deterministic work)
    zero_degs_kernel<<<nblk_nodes, 256>>>();
    count_degs_kernel<<<nblk_edges, 256>>>(src, dst);
    rsqrt_degs_kernel<<<nblk_nodes, 256>>>();
    scan_block_sums_kernel<<<NPART, SCAN_B>>>();
    scan_partials_kernel<<<1, 32>>>();
    scan_final_kernel<<<NPART, SCAN_B>>>();
    fill_csr_kernel<<<nblk_edges, 256>>>(src, dst);

    // Layer 1
    aggregate_kernel<<<nblk_aggw, 256>>>(features, agg);
    gemm_bias_relu_kernel<<<nblk_gemm, 256, GEMM_SMEM>>>(agg, W1, b1, h1);

    // Layer 2
    aggregate_kernel<<<nblk_aggw, 256>>>(h1, agg);
    gemm_bias_relu_kernel<<<nblk_gemm, 256, GEMM_SMEM>>>(agg, W2, b2, out);
}

// round 6
// speedup vs baseline: 1.8245x; 1.0499x over previous
#include <cuda_runtime.h>
#include <cuda_bf16.h>
#include <cstdint>

#define N_NODES 100000
#define N_EDGES 1600000
#define F 128
#define SCAN_B 1024
#define NPART ((N_NODES + SCAN_B - 1) / SCAN_B)   // 98

// ---------------- device scratch (allocation-free rule) ----------------
__device__ __align__(16) float g_agg[(size_t)N_NODES * F];   // 51.2 MB
__device__ __align__(16) float g_h1[(size_t)N_NODES * F];    // 51.2 MB
__device__ int   g_deg_src[N_NODES];
__device__ int   g_deg_dst[N_NODES];
__device__ float g_rs_src[N_NODES];
__device__ float g_rs_dst[N_NODES];
__device__ int   g_rowptr[N_NODES + 1];
__device__ int   g_cursor[N_NODES];
__device__ int   g_col[N_EDGES];                  // 6.4 MB
__device__ int   g_part[NPART];
// Pre-split W as bf16 hi/lo, natural [K=128][N=128] layout. 32 KB each.
__device__ __align__(16) unsigned short g_Whi[2][128 * 128];
__device__ __align__(16) unsigned short g_Wlo[2][128 * 128];

// ---------------- mma.sync helpers (portable PTX, sm_80+) ----------------
__device__ __forceinline__ uint32_t smem_u32(const void* p) {
    uint32_t a;
    asm("{ .reg .u64 t; cvta.to.shared.u64 t, %1; cvt.u32.u64 %0, t; }"
        : "=r"(a) : "l"(p));
    return a;
}
#define LDSM_X4(r, addr) \
    asm volatile("ldmatrix.sync.aligned.m8n8.x4.shared.b16 {%0,%1,%2,%3}, [%4];" \
                 : "=r"((r)[0]), "=r"((r)[1]), "=r"((r)[2]), "=r"((r)[3]) \
                 : "r"(addr))
#define LDSM_X2_T(r, addr) \
    asm volatile("ldmatrix.sync.aligned.m8n8.x2.trans.shared.b16 {%0,%1}, [%2];" \
                 : "=r"((r)[0]), "=r"((r)[1]) : "r"(addr))
#define MMA_BF16(c, a, b) \
    asm volatile("mma.sync.aligned.m16n8k16.row.col.f32.bf16.bf16.f32 " \
                 "{%0,%1,%2,%3}, {%4,%5,%6,%7}, {%8,%9}, {%0,%1,%2,%3};" \
                 : "+f"((c)[0]), "+f"((c)[1]), "+f"((c)[2]), "+f"((c)[3]) \
                 : "r"((a)[0]), "r"((a)[1]), "r"((a)[2]), "r"((a)[3]), \
                   "r"((b)[0]), "r"((b)[1]))

// ---------------- preprocessing kernels ----------------
__global__ void zero_degs_kernel() {
    int i = blockIdx.x * blockDim.x + threadIdx.x;
    if (i < N_NODES) { g_deg_src[i] = 0; g_deg_dst[i] = 0; }
}

// src/dst are int32 (JAX x64-disable downcasts the reference's int64 arrays).
__global__ void count_degs_kernel(const int* __restrict__ src,
                                  const int* __restrict__ dst) {
    int e = blockIdx.x * blockDim.x + threadIdx.x;
    if (e < N_EDGES) {
        atomicAdd(&g_deg_src[src[e]], 1);
        atomicAdd(&g_deg_dst[dst[e]], 1);
    }
}

__global__ void rsqrt_degs_kernel() {
    int i = blockIdx.x * blockDim.x + threadIdx.x;
    if (i < N_NODES) {
        int ds = g_deg_src[i]; if (ds < 1) ds = 1;
        int dd = g_deg_dst[i]; if (dd < 1) dd = 1;
        g_rs_src[i] = rsqrtf((float)ds);
        g_rs_dst[i] = rsqrtf((float)dd);
    }
}

__global__ void scan_block_sums_kernel() {
    __shared__ int sh[SCAN_B];
    int i = blockIdx.x * SCAN_B + threadIdx.x;
    sh[threadIdx.x] = (i < N_NODES) ? g_deg_dst[i] : 0;
    __syncthreads();
    #pragma unroll
    for (int s = SCAN_B / 2; s > 0; s >>= 1) {
        if (threadIdx.x < s) sh[threadIdx.x] += sh[threadIdx.x + s];
        __syncthreads();
    }
    if (threadIdx.x == 0) g_part[blockIdx.x] = sh[0];
}

__global__ void scan_partials_kernel() {
    if (blockIdx.x == 0 && threadIdx.x == 0) {
        int run = 0;
        for (int i = 0; i < NPART; ++i) { int t = g_part[i]; g_part[i] = run; run += t; }
        g_rowptr[N_NODES] = N_EDGES;
    }
}

__global__ void scan_final_kernel() {
    __shared__ int sh[SCAN_B];
    int tid = threadIdx.x;
    int i = blockIdx.x * SCAN_B + tid;
    int v = (i < N_NODES) ? g_deg_dst[i] : 0;
    sh[tid] = v;
    __syncthreads();
    #pragma unroll
    for (int off = 1; off < SCAN_B; off <<= 1) {
        int t = (tid >= off) ? sh[tid - off] : 0;
        __syncthreads();
        sh[tid] += t;
        __syncthreads();
    }
    if (i < N_NODES) {
        int excl = sh[tid] - v + g_part[blockIdx.x];
        g_rowptr[i] = excl;
        g_cursor[i] = excl;
    }
}

__global__ void fill_csr_kernel(const int* __restrict__ src,
                                const int* __restrict__ dst) {
    int e = blockIdx.x * blockDim.x + threadIdx.x;
    if (e < N_EDGES) {
        int pos = atomicAdd(&g_cursor[dst[e]], 1);
        g_col[pos] = src[e];
    }
}

// Split W[k][n] (fp32 [128][128]) into bf16 hi + lo, same layout.
__global__ void build_w_kernel(const float* __restrict__ W,
                               unsigned short* __restrict__ whi,
                               unsigned short* __restrict__ wlo) {
    int idx = blockIdx.x * blockDim.x + threadIdx.x;
    if (idx >= 128 * 128) return;
    float w = W[idx];
    __nv_bfloat16 hb = __float2bfloat16(w);
    __nv_bfloat16 lb = __float2bfloat16(w - __bfloat162float(hb));
    whi[idx] = __bfloat16_as_ushort(hb);
    wlo[idx] = __bfloat16_as_ushort(lb);
}

// ---------------- aggregation (unchanged from R4 — passing at 342us) ----------------
__global__ void __launch_bounds__(256)
aggregate_kernel(const float* __restrict__ h, float* __restrict__ out) {
    int warp = (blockIdx.x * blockDim.x + threadIdx.x) >> 5;
    int lane = threadIdx.x & 31;
    if (warp >= N_NODES) return;

    int beg = __ldg(&g_rowptr[warp]);
    int end = __ldg(&g_rowptr[warp + 1]);

    float4 acc = make_float4(0.f, 0.f, 0.f, 0.f);
    int e = beg;
    for (; e + 1 < end; e += 2) {
        int s0 = __ldg(&g_col[e]);
        int s1 = __ldg(&g_col[e + 1]);
        float r0 = __ldg(&g_rs_src[s0]);
        float r1 = __ldg(&g_rs_src[s1]);
        float4 v0 = __ldg(((const float4*)(h + (size_t)s0 * F)) + lane);
        float4 v1 = __ldg(((const float4*)(h + (size_t)s1 * F)) + lane);
        acc.x = fmaf(r0, v0.x, acc.x); acc.y = fmaf(r0, v0.y, acc.y);
        acc.z = fmaf(r0, v0.z, acc.z); acc.w = fmaf(r0, v0.w, acc.w);
        acc.x = fmaf(r1, v1.x, acc.x); acc.y = fmaf(r1, v1.y, acc.y);
        acc.z = fmaf(r1, v1.z, acc.z); acc.w = fmaf(r1, v1.w, acc.w);
    }
    if (e < end) {
        int s0 = __ldg(&g_col[e]);
        float r0 = __ldg(&g_rs_src[s0]);
        float4 v0 = __ldg(((const float4*)(h + (size_t)s0 * F)) + lane);
        acc.x = fmaf(r0, v0.x, acc.x); acc.y = fmaf(r0, v0.y, acc.y);
        acc.z = fmaf(r0, v0.z, acc.z); acc.w = fmaf(r0, v0.w, acc.w);
    }

    float rd = __ldg(&g_rs_dst[warp]);
    acc.x *= rd; acc.y *= rd; acc.z *= rd; acc.w *= rd;
    ((float4*)(out + (size_t)warp * F))[lane] = acc;
}

// ---------------- tensor-core GEMM via mma.sync, 3-pass bf16 split -------
// out = relu(A @ W + b);  D = Ah*Wh + Al*Wh + Ah*Wl  (fp32 accumulate)
// One 128x128 tile per CTA, 8 warps (16 rows each), 256 threads.
// smem rows padded to 136 bf16 (272 B) -> conflict-free ldmatrix.
#define PADK 136
#define ROWB (PADK * 2)              // 272 bytes
#define TILE_BYTES (128 * ROWB)      // 34816
#define GEMM_SMEM_BYTES (4 * TILE_BYTES)  // 139264

__global__ void __launch_bounds__(256, 1)
mma_gemm_kernel(const float* __restrict__ A,
                const unsigned short* __restrict__ Whi,
                const unsigned short* __restrict__ Wlo,
                const float* __restrict__ bias,
                float* __restrict__ out) {
    extern __shared__ __align__(16) unsigned char smem[];
    unsigned char* sAh = smem;
    unsigned char* sAl = smem + TILE_BYTES;
    unsigned char* sWh = smem + 2 * TILE_BYTES;
    unsigned char* sWl = smem + 3 * TILE_BYTES;

    int tid  = threadIdx.x;
    int wid  = tid >> 5;
    int lane = tid & 31;
    int row0 = blockIdx.x * 128;

    // ---- Copy pre-split W into padded smem (thread: row=tid/2, half=tid&1)
    {
        int r = tid >> 1, hf = tid & 1;
        const uint4* srch = (const uint4*)(Whi + r * 128 + hf * 64);
        const uint4* srcl = (const uint4*)(Wlo + r * 128 + hf * 64);
        uint4* dsth = (uint4*)(sWh + r * ROWB + hf * 128);
        uint4* dstl = (uint4*)(sWl + r * ROWB + hf * 128);
        #pragma unroll
        for (int i = 0; i < 8; ++i) { dsth[i] = __ldg(srch + i); dstl[i] = __ldg(srcl + i); }
    }
    // ---- Convert A tile fp32 -> bf16 hi/lo into padded smem
    {
        int r = tid >> 1, hf = tid & 1;
        int row = row0 + r;
        const float4* arow = (const float4*)(A + (size_t)row * F) + hf * 16;
        unsigned char* dh = sAh + r * ROWB + hf * 128;
        unsigned char* dl = sAl + r * ROWB + hf * 128;
        #pragma unroll
        for (int i = 0; i < 16; ++i) {
            float4 a = make_float4(0.f, 0.f, 0.f, 0.f);
            if (row < N_NODES) a = __ldg(arow + i);
            __nv_bfloat16 h0 = __float2bfloat16(a.x), h1 = __float2bfloat16(a.y);
            __nv_bfloat16 h2 = __float2bfloat16(a.z), h3 = __float2bfloat16(a.w);
            __nv_bfloat16 l0 = __float2bfloat16(a.x - __bfloat162float(h0));
            __nv_bfloat16 l1 = __float2bfloat16(a.y - __bfloat162float(h1));
            __nv_bfloat16 l2 = __float2bfloat16(a.z - __bfloat162float(h2));
            __nv_bfloat16 l3 = __float2bfloat16(a.w - __bfloat162float(h3));
            uint2 ph = make_uint2(
                ((uint32_t)__bfloat16_as_ushort(h1) << 16) | __bfloat16_as_ushort(h0),
                ((uint32_t)__bfloat16_as_ushort(h3) << 16) | __bfloat16_as_ushort(h2));
            uint2 pl = make_uint2(
                ((uint32_t)__bfloat16_as_ushort(l1) << 16) | __bfloat16_as_ushort(l0),
                ((uint32_t)__bfloat16_as_ushort(l3) << 16) | __bfloat16_as_ushort(l2));
            *(uint2*)(dh + i * 8) = ph;
            *(uint2*)(dl + i * 8) = pl;
        }
    }
    __syncthreads();

    // ---- Mainloop: 8 k-steps of k16; per step reuse Wh frag for Ah and Al.
    int m0 = wid * 16;
    float acc[16][4];
    #pragma unroll
    for (int nt = 0; nt < 16; ++nt)
        #pragma unroll
        for (int c = 0; c < 4; ++c) acc[nt][c] = 0.f;

    // ldmatrix A addresses: lane l -> row m0+(l%16), k-byte (l/16)*16
    uint32_t aoff = (uint32_t)(m0 + (lane & 15)) * ROWB + (uint32_t)(lane >> 4) * 16;
    uint32_t ah_base = smem_u32(sAh) + aoff;
    uint32_t al_base = smem_u32(sAl) + aoff;
    // ldmatrix B (trans) addresses: lane l -> W row k0+(l%16), col n0
    uint32_t wrow = (uint32_t)(lane & 15) * ROWB;
    uint32_t wh_base = smem_u32(sWh) + wrow;
    uint32_t wl_base = smem_u32(sWl) + wrow;

    #pragma unroll
    for (int ks = 0; ks < 8; ++ks) {
        uint32_t ah[4], al[4];
        LDSM_X4(ah, ah_base + ks * 32);
        LDSM_X4(al, al_base + ks * 32);
        uint32_t wh_k = wh_base + (uint32_t)ks * 16 * ROWB;
        uint32_t wl_k = wl_base + (uint32_t)ks * 16 * ROWB;
        #pragma unroll
        for (int nt = 0; nt < 16; ++nt) {
            uint32_t bh[2], bl[2];
            LDSM_X2_T(bh, wh_k + nt * 16);
            MMA_BF16(acc[nt], ah, bh);
            MMA_BF16(acc[nt], al, bh);
            LDSM_X2_T(bl, wl_k + nt * 16);
            MMA_BF16(acc[nt], ah, bl);
        }
    }

    // ---- Epilogue: bias + relu, direct to global.
    // Fragment: c0,c1 -> (row l>>2, col 2(l%4)+{0,1}); c2,c3 -> row+8.
    int r0 = row0 + m0 + (lane >> 2);
    int cb = 2 * (lane & 3);
    #pragma unroll
    for (int nt = 0; nt < 16; ++nt) {
        int n = nt * 8 + cb;
        float bx = __ldg(&bias[n]), by = __ldg(&bias[n + 1]);
        if (r0 < N_NODES) {
            float2 o0;
            o0.x = fmaxf(acc[nt][0] + bx, 0.f);
            o0.y = fmaxf(acc[nt][1] + by, 0.f);
            *(float2*)(out + (size_t)r0 * F + n) = o0;
        }
        if (r0 + 8 < N_NODES) {
            float2 o1;
            o1.x = fmaxf(acc[nt][2] + bx, 0.f);
            o1.y = fmaxf(acc[nt][3] + by, 0.f);
            *(float2*)(out + (size_t)(r0 + 8) * F + n) = o1;
        }
    }
}

// ---------------- host launch ----------------
extern "C" void kernel_launch(void* const* d_in, const int* in_sizes, int n_in,
                              void* d_out, int out_size) {
    const float* features = (const float*)d_in[0];
    const float* W1       = (const float*)d_in[1];
    const float* b1       = (const float*)d_in[2];
    const float* W2       = (const float*)d_in[3];
    const float* b2       = (const float*)d_in[4];
    const int*   src      = (const int*)d_in[5];
    const int*   dst      = (const int*)d_in[6];
    float*       out      = (float*)d_out;

    float *agg = nullptr, *h1 = nullptr;
    unsigned short *whi = nullptr, *wlo = nullptr;
    cudaGetSymbolAddress((void**)&agg, g_agg);
    cudaGetSymbolAddress((void**)&h1,  g_h1);
    cudaGetSymbolAddress((void**)&whi, g_Whi);
    cudaGetSymbolAddress((void**)&wlo, g_Wlo);

    cudaFuncSetAttribute(mma_gemm_kernel,
                         cudaFuncAttributeMaxDynamicSharedMemorySize,
                         GEMM_SMEM_BYTES);

    int nblk_nodes = (N_NODES + 255) / 256;
    int nblk_edges = (N_EDGES + 255) / 256;
    int nblk_aggw  = (N_NODES * 32 + 255) / 256;   // one warp per node
    int nblk_gemm  = (N_NODES + 127) / 128;        // 782

    // Preprocessing: degrees, CSR, W split (deterministic each call)
    zero_degs_kernel<<<nblk_nodes, 256>>>();
    count_degs_kernel<<<nblk_edges, 256>>>(src, dst);
    rsqrt_degs_kernel<<<nblk_nodes, 256>>>();
    scan_block_sums_kernel<<<NPART, SCAN_B>>>();
    scan_partials_kernel<<<1, 32>>>();
    scan_final_kernel<<<NPART, SCAN_B>>>();
    fill_csr_kernel<<<nblk_edges, 256>>>(src, dst);
    build_w_kernel<<<64, 256>>>(W1, whi, wlo);
    build_w_kernel<<<64, 256>>>(W2, whi + 128 * 128, wlo + 128 * 128);

    // Layer 1
    aggregate_kernel<<<nblk_aggw, 256>>>(features, agg);
    mma_gemm_kernel<<<nblk_gemm, 256, GEMM_SMEM_BYTES>>>(agg, whi, wlo, b1, h1);

    // Layer 2
    aggregate_kernel<<<nblk_aggw, 256>>>(h1, agg);
    mma_gemm_kernel<<<nblk_gemm, 256, GEMM_SMEM_BYTES>>>(agg, whi + 128 * 128,
                                                         wlo + 128 * 128, b2, out);
}

// round 7
// speedup vs baseline: 1.9894x; 1.0904x over previous
#include <cuda_runtime.h>
#include <cuda_bf16.h>
#include <cuda_fp16.h>
#include <cstdint>

#define N_NODES 100000
#define N_EDGES 1600000
#define F 128
#define SCAN_B 1024
#define NPART ((N_NODES + SCAN_B - 1) / SCAN_B)   // 98

// ---------------- device scratch (allocation-free rule) ----------------
__device__ __align__(16) float  g_agg[(size_t)N_NODES * F];  // 51.2 MB
__device__ __align__(16) __half g_h16[(size_t)N_NODES * F];  // 25.6 MB (shared: conv out, gemm1 out)
__device__ int   g_deg_src[N_NODES];
__device__ int   g_deg_dst[N_NODES];
__device__ float g_rs_src[N_NODES];
__device__ float g_rs_dst[N_NODES];
__device__ int   g_rowptr[N_NODES + 1];
__device__ int   g_cursor[N_NODES];
__device__ int   g_col[N_EDGES];                  // 6.4 MB
__device__ int   g_part[NPART];
// Pre-split W as bf16 hi/lo, natural [K=128][N=128] layout. 32 KB each.
__device__ __align__(16) unsigned short g_Whi[2][128 * 128];
__device__ __align__(16) unsigned short g_Wlo[2][128 * 128];

// ---------------- mma.sync helpers (portable PTX, sm_80+) ----------------
__device__ __forceinline__ uint32_t smem_u32(const void* p) {
    uint32_t a;
    asm("{ .reg .u64 t; cvta.to.shared.u64 t, %1; cvt.u32.u64 %0, t; }"
        : "=r"(a) : "l"(p));
    return a;
}
#define LDSM_X4(r, addr) \
    asm volatile("ldmatrix.sync.aligned.m8n8.x4.shared.b16 {%0,%1,%2,%3}, [%4];" \
                 : "=r"((r)[0]), "=r"((r)[1]), "=r"((r)[2]), "=r"((r)[3]) \
                 : "r"(addr))
#define LDSM_X2_T(r, addr) \
    asm volatile("ldmatrix.sync.aligned.m8n8.x2.trans.shared.b16 {%0,%1}, [%2];" \
                 : "=r"((r)[0]), "=r"((r)[1]) : "r"(addr))
#define MMA_BF16(c, a, b) \
    asm volatile("mma.sync.aligned.m16n8k16.row.col.f32.bf16.bf16.f32 " \
                 "{%0,%1,%2,%3}, {%4,%5,%6,%7}, {%8,%9}, {%0,%1,%2,%3};" \
                 : "+f"((c)[0]), "+f"((c)[1]), "+f"((c)[2]), "+f"((c)[3]) \
                 : "r"((a)[0]), "r"((a)[1]), "r"((a)[2]), "r"((a)[3]), \
                   "r"((b)[0]), "r"((b)[1]))

// ---------------- preprocessing kernels ----------------
__global__ void zero_degs_kernel() {
    int i = blockIdx.x * blockDim.x + threadIdx.x;
    if (i < N_NODES) { g_deg_src[i] = 0; g_deg_dst[i] = 0; }
}

// src/dst are int32 (JAX x64-disable downcasts the reference's int64 arrays).
__global__ void count_degs_kernel(const int* __restrict__ src,
                                  const int* __restrict__ dst) {
    int e = blockIdx.x * blockDim.x + threadIdx.x;
    if (e < N_EDGES) {
        atomicAdd(&g_deg_src[src[e]], 1);
        atomicAdd(&g_deg_dst[dst[e]], 1);
    }
}

__global__ void rsqrt_degs_kernel() {
    int i = blockIdx.x * blockDim.x + threadIdx.x;
    if (i < N_NODES) {
        int ds = g_deg_src[i]; if (ds < 1) ds = 1;
        int dd = g_deg_dst[i]; if (dd < 1) dd = 1;
        g_rs_src[i] = rsqrtf((float)ds);
        g_rs_dst[i] = rsqrtf((float)dd);
    }
}

__global__ void scan_block_sums_kernel() {
    __shared__ int sh[SCAN_B];
    int i = blockIdx.x * SCAN_B + threadIdx.x;
    sh[threadIdx.x] = (i < N_NODES) ? g_deg_dst[i] : 0;
    __syncthreads();
    #pragma unroll
    for (int s = SCAN_B / 2; s > 0; s >>= 1) {
        if (threadIdx.x < s) sh[threadIdx.x] += sh[threadIdx.x + s];
        __syncthreads();
    }
    if (threadIdx.x == 0) g_part[blockIdx.x] = sh[0];
}

__global__ void scan_partials_kernel() {
    if (blockIdx.x == 0 && threadIdx.x == 0) {
        int run = 0;
        for (int i = 0; i < NPART; ++i) { int t = g_part[i]; g_part[i] = run; run += t; }
        g_rowptr[N_NODES] = N_EDGES;
    }
}

__global__ void scan_final_kernel() {
    __shared__ int sh[SCAN_B];
    int tid = threadIdx.x;
    int i = blockIdx.x * SCAN_B + tid;
    int v = (i < N_NODES) ? g_deg_dst[i] : 0;
    sh[tid] = v;
    __syncthreads();
    #pragma unroll
    for (int off = 1; off < SCAN_B; off <<= 1) {
        int t = (tid >= off) ? sh[tid - off] : 0;
        __syncthreads();
        sh[tid] += t;
        __syncthreads();
    }
    if (i < N_NODES) {
        int excl = sh[tid] - v + g_part[blockIdx.x];
        g_rowptr[i] = excl;
        g_cursor[i] = excl;
    }
}

__global__ void fill_csr_kernel(const int* __restrict__ src,
                                const int* __restrict__ dst) {
    int e = blockIdx.x * blockDim.x + threadIdx.x;
    if (e < N_EDGES) {
        int pos = atomicAdd(&g_cursor[dst[e]], 1);
        g_col[pos] = src[e];
    }
}

// Split W[k][n] (fp32 [128][128]) into bf16 hi + lo, same layout.
__global__ void build_w_kernel(const float* __restrict__ W,
                               unsigned short* __restrict__ whi,
                               unsigned short* __restrict__ wlo) {
    int idx = blockIdx.x * blockDim.x + threadIdx.x;
    if (idx >= 128 * 128) return;
    float w = W[idx];
    __nv_bfloat16 hb = __float2bfloat16(w);
    __nv_bfloat16 lb = __float2bfloat16(w - __bfloat162float(hb));
    whi[idx] = __bfloat16_as_ushort(hb);
    wlo[idx] = __bfloat16_as_ushort(lb);
}

// Convert fp32 features -> fp16, pre-scaled by rs_src[row].
__global__ void conv_h16_kernel(const float* __restrict__ h) {
    size_t i = (size_t)blockIdx.x * blockDim.x + threadIdx.x;  // float4 index
    if (i >= (size_t)N_NODES * (F / 4)) return;
    int row = (int)(i >> 5);                                   // 32 float4 per row
    float rs = __ldg(&g_rs_src[row]);
    float4 v = __ldg(((const float4*)h) + i);
    __half2 a = __floats2half2_rn(v.x * rs, v.y * rs);
    __half2 b = __floats2half2_rn(v.z * rs, v.w * rs);
    *(__half2*)(g_h16 + i * 4)     = a;
    *(__half2*)(g_h16 + i * 4 + 2) = b;
}

// ---------------- aggregation: fp16 gather, half-warp per edge ----------------
// agg[n,:] = rs_dst[n] * sum_{s in N_in(n)} h16[s,:]   (h16 pre-scaled by rs_src)
__global__ void __launch_bounds__(256)
aggregate16_kernel(float* __restrict__ out) {
    int warp = (blockIdx.x * blockDim.x + threadIdx.x) >> 5;
    int lane = threadIdx.x & 31;
    if (warp >= N_NODES) return;

    int hw = lane >> 4;          // which edge slot (0/1)
    int j  = lane & 15;          // 16B chunk: halves [j*8, j*8+8)

    int beg = __ldg(&g_rowptr[warp]);
    int end = __ldg(&g_rowptr[warp + 1]);

    float acc[8];
    #pragma unroll
    for (int i = 0; i < 8; ++i) acc[i] = 0.f;

    // half-warp hw processes edges beg+hw, beg+hw+2, ... ; unroll 2 -> 4 loads in flight/warp
    int e = beg + hw;
    for (; e + 2 < end; e += 4) {
        int s0 = __ldg(&g_col[e]);
        int s1 = __ldg(&g_col[e + 2]);
        uint4 v0 = __ldg((const uint4*)(g_h16 + (size_t)s0 * F + j * 8));
        uint4 v1 = __ldg((const uint4*)(g_h16 + (size_t)s1 * F + j * 8));
        const __half2* p0 = (const __half2*)&v0;
        const __half2* p1 = (const __half2*)&v1;
        #pragma unroll
        for (int q = 0; q < 4; ++q) {
            float2 f0 = __half22float2(p0[q]);
            float2 f1 = __half22float2(p1[q]);
            acc[2 * q]     += f0.x + f1.x;
            acc[2 * q + 1] += f0.y + f1.y;
        }
    }
    if (e < end) {
        int s0 = __ldg(&g_col[e]);
        uint4 v0 = __ldg((const uint4*)(g_h16 + (size_t)s0 * F + j * 8));
        const __half2* p0 = (const __half2*)&v0;
        #pragma unroll
        for (int q = 0; q < 4; ++q) {
            float2 f0 = __half22float2(p0[q]);
            acc[2 * q]     += f0.x;
            acc[2 * q + 1] += f0.y;
        }
    }

    // combine the two half-warps
    #pragma unroll
    for (int i = 0; i < 8; ++i)
        acc[i] += __shfl_xor_sync(0xFFFFFFFFu, acc[i], 16);

    if (hw == 0) {
        float rd = __ldg(&g_rs_dst[warp]);
        float4 o0 = make_float4(acc[0] * rd, acc[1] * rd, acc[2] * rd, acc[3] * rd);
        float4 o1 = make_float4(acc[4] * rd, acc[5] * rd, acc[6] * rd, acc[7] * rd);
        float4* op = (float4*)(out + (size_t)warp * F + j * 8);
        op[0] = o0;
        op[1] = o1;
    }
}

// ---------------- tensor-core GEMM via mma.sync, 3-pass bf16 split -------
// D = Ah*Wh + Al*Wh + Ah*Wl (fp32 accum); relu(D + b).
// HALF_OUT=1: write __half, pre-scaled by rs_src[row] (feeds next aggregate).
// HALF_OUT=0: write fp32 (final output).
#define PADK 136
#define ROWB (PADK * 2)              // 272 bytes
#define TILE_BYTES (128 * ROWB)      // 34816
#define GEMM_SMEM_BYTES (4 * TILE_BYTES)  // 139264

template <int HALF_OUT>
__global__ void __launch_bounds__(256, 1)
mma_gemm_kernel(const float* __restrict__ A,
                const unsigned short* __restrict__ Whi,
                const unsigned short* __restrict__ Wlo,
                const float* __restrict__ bias,
                float* __restrict__ out32,
                __half* __restrict__ out16) {
    extern __shared__ __align__(16) unsigned char smem[];
    unsigned char* sAh = smem;
    unsigned char* sAl = smem + TILE_BYTES;
    unsigned char* sWh = smem + 2 * TILE_BYTES;
    unsigned char* sWl = smem + 3 * TILE_BYTES;

    int tid  = threadIdx.x;
    int wid  = tid >> 5;
    int lane = tid & 31;
    int row0 = blockIdx.x * 128;

    {
        int r = tid >> 1, hf = tid & 1;
        const uint4* srch = (const uint4*)(Whi + r * 128 + hf * 64);
        const uint4* srcl = (const uint4*)(Wlo + r * 128 + hf * 64);
        uint4* dsth = (uint4*)(sWh + r * ROWB + hf * 128);
        uint4* dstl = (uint4*)(sWl + r * ROWB + hf * 128);
        #pragma unroll
        for (int i = 0; i < 8; ++i) { dsth[i] = __ldg(srch + i); dstl[i] = __ldg(srcl + i); }
    }
    {
        int r = tid >> 1, hf = tid & 1;
        int row = row0 + r;
        const float4* arow = (const float4*)(A + (size_t)row * F) + hf * 16;
        unsigned char* dh = sAh + r * ROWB + hf * 128;
        unsigned char* dl = sAl + r * ROWB + hf * 128;
        #pragma unroll
        for (int i = 0; i < 16; ++i) {
            float4 a = make_float4(0.f, 0.f, 0.f, 0.f);
            if (row < N_NODES) a = __ldg(arow + i);
            __nv_bfloat16 h0 = __float2bfloat16(a.x), h1 = __float2bfloat16(a.y);
            __nv_bfloat16 h2 = __float2bfloat16(a.z), h3 = __float2bfloat16(a.w);
            __nv_bfloat16 l0 = __float2bfloat16(a.x - __bfloat162float(h0));
            __nv_bfloat16 l1 = __float2bfloat16(a.y - __bfloat162float(h1));
            __nv_bfloat16 l2 = __float2bfloat16(a.z - __bfloat162float(h2));
            __nv_bfloat16 l3 = __float2bfloat16(a.w - __bfloat162float(h3));
            uint2 ph = make_uint2(
                ((uint32_t)__bfloat16_as_ushort(h1) << 16) | __bfloat16_as_ushort(h0),
                ((uint32_t)__bfloat16_as_ushort(h3) << 16) | __bfloat16_as_ushort(h2));
            uint2 pl = make_uint2(
                ((uint32_t)__bfloat16_as_ushort(l1) << 16) | __bfloat16_as_ushort(l0),
                ((uint32_t)__bfloat16_as_ushort(l3) << 16) | __bfloat16_as_ushort(l2));
            *(uint2*)(dh + i * 8) = ph;
            *(uint2*)(dl + i * 8) = pl;
        }
    }
    __syncthreads();

    int m0 = wid * 16;
    float acc[16][4];
    #pragma unroll
    for (int nt = 0; nt < 16; ++nt)
        #pragma unroll
        for (int c = 0; c < 4; ++c) acc[nt][c] = 0.f;

    uint32_t aoff = (uint32_t)(m0 + (lane & 15)) * ROWB + (uint32_t)(lane >> 4) * 16;
    uint32_t ah_base = smem_u32(sAh) + aoff;
    uint32_t al_base = smem_u32(sAl) + aoff;
    uint32_t wrow = (uint32_t)(lane & 15) * ROWB;
    uint32_t wh_base = smem_u32(sWh) + wrow;
    uint32_t wl_base = smem_u32(sWl) + wrow;

    #pragma unroll
    for (int ks = 0; ks < 8; ++ks) {
        uint32_t ah[4], al[4];
        LDSM_X4(ah, ah_base + ks * 32);
        LDSM_X4(al, al_base + ks * 32);
        uint32_t wh_k = wh_base + (uint32_t)ks * 16 * ROWB;
        uint32_t wl_k = wl_base + (uint32_t)ks * 16 * ROWB;
        #pragma unroll
        for (int nt = 0; nt < 16; ++nt) {
            uint32_t bh[2], bl[2];
            LDSM_X2_T(bh, wh_k + nt * 16);
            MMA_BF16(acc[nt], ah, bh);
            MMA_BF16(acc[nt], al, bh);
            LDSM_X2_T(bl, wl_k + nt * 16);
            MMA_BF16(acc[nt], ah, bl);
        }
    }

    // Epilogue: bias + relu (+optional rs_src prescale, fp16 store).
    int r0 = row0 + m0 + (lane >> 2);
    int cb = 2 * (lane & 3);
    float rs0 = 0.f, rs1 = 0.f;
    if (HALF_OUT) {
        if (r0 < N_NODES)     rs0 = __ldg(&g_rs_src[r0]);
        if (r0 + 8 < N_NODES) rs1 = __ldg(&g_rs_src[r0 + 8]);
    }
    #pragma unroll
    for (int nt = 0; nt < 16; ++nt) {
        int n = nt * 8 + cb;
        float bx = __ldg(&bias[n]), by = __ldg(&bias[n + 1]);
        float v0x = fmaxf(acc[nt][0] + bx, 0.f);
        float v0y = fmaxf(acc[nt][1] + by, 0.f);
        float v1x = fmaxf(acc[nt][2] + bx, 0.f);
        float v1y = fmaxf(acc[nt][3] + by, 0.f);
        if (HALF_OUT) {
            if (r0 < N_NODES)
                *(__half2*)(out16 + (size_t)r0 * F + n) = __floats2half2_rn(v0x * rs0, v0y * rs0);
            if (r0 + 8 < N_NODES)
                *(__half2*)(out16 + (size_t)(r0 + 8) * F + n) = __floats2half2_rn(v1x * rs1, v1y * rs1);
        } else {
            if (r0 < N_NODES)
                *(float2*)(out32 + (size_t)r0 * F + n) = make_float2(v0x, v0y);
            if (r0 + 8 < N_NODES)
                *(float2*)(out32 + (size_t)(r0 + 8) * F + n) = make_float2(v1x, v1y);
        }
    }
}

// ---------------- host launch ----------------
extern "C" void kernel_launch(void* const* d_in, const int* in_sizes, int n_in,
                              void* d_out, int out_size) {
    const float* features = (const float*)d_in[0];
    const float* W1       = (const float*)d_in[1];
    const float* b1       = (const float*)d_in[2];
    const float* W2       = (const float*)d_in[3];
    const float* b2       = (const float*)d_in[4];
    const int*   src      = (const int*)d_in[5];
    const int*   dst      = (const int*)d_in[6];
    float*       out      = (float*)d_out;

    float *agg = nullptr;
    __half *h16 = nullptr;
    unsigned short *whi = nullptr, *wlo = nullptr;
    cudaGetSymbolAddress((void**)&agg, g_agg);
    cudaGetSymbolAddress((void**)&h16, g_h16);
    cudaGetSymbolAddress((void**)&whi, g_Whi);
    cudaGetSymbolAddress((void**)&wlo, g_Wlo);

    cudaFuncSetAttribute(mma_gemm_kernel<0>,
                         cudaFuncAttributeMaxDynamicSharedMemorySize, GEMM_SMEM_BYTES);
    cudaFuncSetAttribute(mma_gemm_kernel<1>,
                         cudaFuncAttributeMaxDynamicSharedMemorySize, GEMM_SMEM_BYTES);

    int nblk_nodes = (N_NODES + 255) / 256;
    int nblk_edges = (N_EDGES + 255) / 256;
    int nblk_conv  = (int)(((size_t)N_NODES * (F / 4) + 255) / 256);
    int nblk_aggw  = (N_NODES * 32 + 255) / 256;   // one warp per node
    int nblk_gemm  = (N_NODES + 127) / 128;        // 782

    // Preprocessing: degrees, CSR, W split (deterministic each call)
    zero_degs_kernel<<<nblk_nodes, 256>>>();
    count_degs_kernel<<<nblk_edges, 256>>>(src, dst);
    rsqrt_degs_kernel<<<nblk_nodes, 256>>>();
    scan_block_sums_kernel<<<NPART, SCAN_B>>>();
    scan_partials_kernel<<<1, 32>>>();
    scan_final_kernel<<<NPART, SCAN_B>>>();
    fill_csr_kernel<<<nblk_edges, 256>>>(src, dst);
    build_w_kernel<<<64, 256>>>(W1, whi, wlo);
    build_w_kernel<<<64, 256>>>(W2, whi + 128 * 128, wlo + 128 * 128);

    // Layer 1: features -> fp16 (pre-scaled) -> aggregate -> GEMM (fp16 out, pre-scaled)
    conv_h16_kernel<<<nblk_conv, 256>>>(features);
    aggregate16_kernel<<<nblk_aggw, 256>>>(agg);
    mma_gemm_kernel<1><<<nblk_gemm, 256, GEMM_SMEM_BYTES>>>(agg, whi, wlo, b1, nullptr, h16);

    // Layer 2: aggregate fp16 h1 -> GEMM (fp32 out)
    aggregate16_kernel<<<nblk_aggw, 256>>>(agg);
    mma_gemm_kernel<0><<<nblk_gemm, 256, GEMM_SMEM_BYTES>>>(agg, whi + 128 * 128,
                                                            wlo + 128 * 128, b2, out, nullptr);
}